// round 15
// baseline (speedup 1.0000x reference)
#include <cuda_runtime.h>

// KDE Gaussian: samples (B=2, S=4096, 2), locations (m=8192, 2)
// out[m,b] = sum_s exp(-|s-l|^2/(2 bw^2));  pdf[m,b] = out[m,b] / sum_m out[m,b]
//
// e = q + P + Lx*Sx + Ly*Sy = -k*dist^2 <= 0  (range-safe)
// HYBRID exp: 6 of 8 exps via MUFU ex2 (packed add2 accumulate), 2 via
// packed-f32x2 polynomial 2^x on the FMA+ALU pipes. 6:2 is the analytic
// optimum: MUFU 48 / FMA 46 cyc per 8 exps (4:4 -> FMA 60; 8:0 -> MUFU 64).
// Cross-block reduction via exact u64 fixed-point atomics (deterministic:
// integer adds commute; f32 * 2^32 -> u64 conversion is exact).

#define S_TOT   4096
#define M_TOT   8192
#define B_TOT   2
#define NSPLIT  32
#define CHUNK   (S_TOT / NSPLIT)   // 128
#define TPB     256
#define M_TILE  512                // 2 locations per thread
#define MTILES  (M_TOT / M_TILE)   // 16

#define KLOG    18.033688f         // log2(e) / (2*bw^2), bw=0.2
#define FIXSCALE 4294967296.0f     // 2^32

typedef unsigned long long u64;
typedef unsigned int u32;

__device__ u64 g_acc[B_TOT * M_TOT];   // fixed-point sums, zero at entry
__device__ u64 g_norm[B_TOT];          // fixed-point per-batch norms, zero at entry

__device__ __forceinline__ float ex2(float x) {
    float r; asm("ex2.approx.ftz.f32 %0, %1;" : "=f"(r) : "f"(x)); return r;
}
__device__ __forceinline__ u64 pack2(float lo, float hi) {
    u64 r; asm("mov.b64 %0, {%1, %2};" : "=l"(r) : "f"(lo), "f"(hi)); return r;
}
__device__ __forceinline__ void unpack2(u64 v, float& lo, float& hi) {
    asm("mov.b64 {%0, %1}, %2;" : "=f"(lo), "=f"(hi) : "l"(v));
}
__device__ __forceinline__ u64 fma2(u64 a, u64 b, u64 c) {
    u64 d; asm("fma.rn.f32x2 %0, %1, %2, %3;" : "=l"(d) : "l"(a), "l"(b), "l"(c)); return d;
}
__device__ __forceinline__ u64 add2(u64 a, u64 b) {
    u64 d; asm("add.rn.f32x2 %0, %1, %2;" : "=l"(d) : "l"(a), "l"(b)); return d;
}

// Packed 2^x for two lanes, x <= 0 (deg-4 Taylor on [-0.5,0.5]).
__device__ __forceinline__ u64 exp2_poly2(u64 x,
                                          u64 MAGIC2, u64 NEGMAGIC2, u64 NEGONE2,
                                          u64 C4, u64 C3, u64 C2, u64 C1, u64 C0) {
    float xl, xh;
    unpack2(x, xl, xh);
    xl = fmaxf(xl, -126.0f);               // FMNMX (alu pipe)
    xh = fmaxf(xh, -126.0f);
    u64 xc = pack2(xl, xh);
    u64 t  = add2(xc, MAGIC2);             // round-to-int in mantissa
    u64 r  = add2(t, NEGMAGIC2);           // rounded integer value as float
    u64 f  = fma2(r, NEGONE2, xc);         // frac in [-0.5, 0.5]
    u64 p  = fma2(C4, f, C3);
    p = fma2(p, f, C2);
    p = fma2(p, f, C1);
    p = fma2(p, f, C0);
    // splice 2^ei into the float bits (ALU pipe)
    u32 tl = (u32)t, th = (u32)(t >> 32);
    float pl, ph;
    unpack2(p, pl, ph);
    int el = (int)(tl - 0x4B400000u);
    int eh = (int)(th - 0x4B400000u);
    u32 rl = __float_as_uint(pl) + ((u32)el << 23);
    u32 rh = __float_as_uint(ph) + ((u32)eh << 23);
    return pack2(__uint_as_float(rl), __uint_as_float(rh));
}

__global__ __launch_bounds__(TPB)
void kde_partial_kernel(const float* __restrict__ samples,
                        const float* __restrict__ locs) {
    __shared__ ulonglong2 shXY[CHUNK / 2];   // [Sx0,Sx1 | Sy0,Sy1] per 2 samples
    __shared__ u64        shP [CHUNK / 2];   // [P0,P1]
    __shared__ float      wred[TPB / 32];

    const int y     = blockIdx.y;      // 0..63
    const int b     = y >> 5;
    const int chunk = y & 31;
    const int tid   = threadIdx.x;

    if (tid < CHUNK / 2) {
        const float4 s2 = reinterpret_cast<const float4*>(samples)
                              [(b * S_TOT + chunk * CHUNK) / 2 + tid];
        float4 xy = make_float4(2.0f * KLOG * s2.x, 2.0f * KLOG * s2.z,
                                2.0f * KLOG * s2.y, 2.0f * KLOG * s2.w);
        *reinterpret_cast<float4*>(&shXY[tid]) = xy;
        shP[tid] = pack2(-KLOG * (s2.x * s2.x + s2.y * s2.y),
                         -KLOG * (s2.z * s2.z + s2.w * s2.w));
    }
    __syncthreads();

    const int m0 = blockIdx.x * M_TILE + tid;
    const int m1 = m0 + TPB;
    const float2 L0 = reinterpret_cast<const float2*>(locs)[m0];
    const float2 L1 = reinterpret_cast<const float2*>(locs)[m1];
    const u64 Lx0 = pack2(L0.x, L0.x), Ly0 = pack2(L0.y, L0.y);
    const u64 Lx1 = pack2(L1.x, L1.x), Ly1 = pack2(L1.y, L1.y);
    const float q0 = -KLOG * (L0.x * L0.x + L0.y * L0.y);
    const float q1 = -KLOG * (L1.x * L1.x + L1.y * L1.y);
    const u64 qq0 = pack2(q0, q0), qq1 = pack2(q1, q1);

    const u64 MAGIC2    = pack2(12582912.0f, 12582912.0f);
    const u64 NEGMAGIC2 = pack2(-12582912.0f, -12582912.0f);
    const u64 NEGONE2   = pack2(-1.0f, -1.0f);
    const u64 C4 = pack2(0.009618129f, 0.009618129f);
    const u64 C3 = pack2(0.055504109f, 0.055504109f);
    const u64 C2 = pack2(0.240226507f, 0.240226507f);
    const u64 C1 = pack2(0.693147181f, 0.693147181f);
    const u64 C0 = pack2(1.0f, 1.0f);

    u64 accA0 = 0, accA1 = 0;   // location 0 (MUFU path)
    u64 accB0 = 0;              // location 1 (MUFU path)
    u64 accB1 = 0;              // location 1 (poly path)
    #pragma unroll 2
    for (int i = 0; i < CHUNK / 2; i += 2) {
        ulonglong2 xy0 = shXY[i];
        ulonglong2 xy1 = shXY[i + 1];
        u64 p0 = shP[i];
        u64 p1 = shP[i + 1];

        u64 eA0 = add2(fma2(Ly0, xy0.y, fma2(Lx0, xy0.x, p0)), qq0);
        u64 eA1 = add2(fma2(Ly0, xy1.y, fma2(Lx0, xy1.x, p1)), qq0);
        u64 eB0 = add2(fma2(Ly1, xy0.y, fma2(Lx1, xy0.x, p0)), qq1);
        u64 eB1 = add2(fma2(Ly1, xy1.y, fma2(Lx1, xy1.x, p1)), qq1);

        float a0, a1, a2, a3, b0, b1;
        unpack2(eA0, a0, a1);  unpack2(eA1, a2, a3);
        unpack2(eB0, b0, b1);
        accA0 = add2(accA0, pack2(ex2(a0), ex2(a1)));
        accA1 = add2(accA1, pack2(ex2(a2), ex2(a3)));
        accB0 = add2(accB0, pack2(ex2(b0), ex2(b1)));
        accB1 = add2(accB1, exp2_poly2(eB1, MAGIC2, NEGMAGIC2, NEGONE2,
                                       C4, C3, C2, C1, C0));
    }

    float r0, r1, r2, r3;
    unpack2(accA0, r0, r1); unpack2(accA1, r2, r3);
    const float v0 = (r0 + r1) + (r2 + r3);
    unpack2(accB0, r0, r1); unpack2(accB1, r2, r3);
    const float v1 = (r0 + r1) + (r2 + r3);

    // exact fixed-point accumulation (deterministic: integer adds commute)
    atomicAdd(&g_acc[b * M_TOT + m0], __float2ull_rn(v0 * FIXSCALE));
    atomicAdd(&g_acc[b * M_TOT + m1], __float2ull_rn(v1 * FIXSCALE));

    // block contribution to the batch norm (one atomic per block)
    float w = v0 + v1;
    #pragma unroll
    for (int off = 16; off > 0; off >>= 1)
        w += __shfl_xor_sync(0xFFFFFFFFu, w, off);
    if ((tid & 31) == 0) wred[tid >> 5] = w;
    __syncthreads();
    if (tid == 0) {
        float s = 0.f;
        #pragma unroll
        for (int j = 0; j < TPB / 32; j++) s += wred[j];
        atomicAdd(&g_norm[b], __float2ull_rn(s * FIXSCALE));
    }
}

// Finalize: 16K threads, one output each; L2-resident reads;
// self-cleans the accumulators for the next graph replay.
__global__ __launch_bounds__(256)
void kde_finalize_kernel(float* __restrict__ out) {
    const int g = blockIdx.x * 256 + threadIdx.x;  // 0..16383
    const int b = g >> 13;
    const int m = g & (M_TOT - 1);

    const u64 acc  = g_acc[g];
    const u64 nrm  = g_norm[b];
    out[m * B_TOT + b] = (float)acc * (1.0f / (float)nrm);

    g_acc[g] = 0ull;                   // self-clean for next replay
    if (g < B_TOT) g_norm[g] = 0ull;
}

extern "C" void kernel_launch(void* const* d_in, const int* in_sizes, int n_in,
                              void* d_out, int out_size) {
    const float* samples = (const float*)d_in[0];   // (2, 4096, 2) f32
    const float* locs    = (const float*)d_in[1];   // (8192, 2)  f32
    float* out = (float*)d_out;                     // (1, 8192, 2) f32

    dim3 g1(MTILES, NSPLIT * B_TOT);                // (16, 64) = 1024 blocks
    kde_partial_kernel<<<g1, TPB>>>(samples, locs);
    kde_finalize_kernel<<<(M_TOT * B_TOT) / 256, 256>>>(out);
}

// round 16
// speedup vs baseline: 1.0084x; 1.0084x over previous
#include <cuda_runtime.h>

// KDE Gaussian: samples (B=2, S=4096, 2), locations (m=8192, 2)
// out[m,b] = sum_s exp(-|s-l|^2/(2 bw^2));  pdf[m,b] = out[m,b] / sum_m out[m,b]
//
// e = q + P + Lx*Sx + Ly*Sy = -k*dist^2 <= 0  (range-safe)
// HYBRID exp: 6 of 8 exps via MUFU ex2 (packed add2 accumulate), 2 via
// packed-f32x2 polynomial 2^x on the FMA+ALU pipes. 6:2 is the analytic
// optimum: MUFU 48 / FMA 46 cyc per 8 exps (4:4 -> FMA 60; 8:0 -> MUFU 64;
// 5:3 -> FMA 53). Cross-block reduction via exact u64 fixed-point atomics
// (deterministic: integer adds commute; f32 * 2^32 -> u64 is exact).

#define S_TOT   4096
#define M_TOT   8192
#define B_TOT   2
#define NSPLIT  32
#define CHUNK   (S_TOT / NSPLIT)   // 128
#define TPB     256
#define M_TILE  512                // 2 locations per thread
#define MTILES  (M_TOT / M_TILE)   // 16

#define KLOG    18.033688f         // log2(e) / (2*bw^2), bw=0.2
#define FIXSCALE 4294967296.0f     // 2^32

typedef unsigned long long u64;
typedef unsigned int u32;

__device__ u64 g_acc[B_TOT * M_TOT];   // fixed-point sums, zero at entry
__device__ u64 g_norm[B_TOT];          // fixed-point per-batch norms, zero at entry

__device__ __forceinline__ float ex2(float x) {
    float r; asm("ex2.approx.ftz.f32 %0, %1;" : "=f"(r) : "f"(x)); return r;
}
__device__ __forceinline__ u64 pack2(float lo, float hi) {
    u64 r; asm("mov.b64 %0, {%1, %2};" : "=l"(r) : "f"(lo), "f"(hi)); return r;
}
__device__ __forceinline__ void unpack2(u64 v, float& lo, float& hi) {
    asm("mov.b64 {%0, %1}, %2;" : "=f"(lo), "=f"(hi) : "l"(v));
}
__device__ __forceinline__ u64 fma2(u64 a, u64 b, u64 c) {
    u64 d; asm("fma.rn.f32x2 %0, %1, %2, %3;" : "=l"(d) : "l"(a), "l"(b), "l"(c)); return d;
}
__device__ __forceinline__ u64 add2(u64 a, u64 b) {
    u64 d; asm("add.rn.f32x2 %0, %1, %2;" : "=l"(d) : "l"(a), "l"(b)); return d;
}

// Packed 2^x for two lanes, x <= 0 (deg-4 Taylor on [-0.5,0.5]).
__device__ __forceinline__ u64 exp2_poly2(u64 x,
                                          u64 MAGIC2, u64 NEGMAGIC2, u64 NEGONE2,
                                          u64 C4, u64 C3, u64 C2, u64 C1, u64 C0) {
    float xl, xh;
    unpack2(x, xl, xh);
    xl = fmaxf(xl, -126.0f);               // FMNMX (alu pipe)
    xh = fmaxf(xh, -126.0f);
    u64 xc = pack2(xl, xh);
    u64 t  = add2(xc, MAGIC2);             // round-to-int in mantissa
    u64 r  = add2(t, NEGMAGIC2);           // rounded integer value as float
    u64 f  = fma2(r, NEGONE2, xc);         // frac in [-0.5, 0.5]
    u64 p  = fma2(C4, f, C3);
    p = fma2(p, f, C2);
    p = fma2(p, f, C1);
    p = fma2(p, f, C0);
    // splice 2^ei into the float bits (ALU pipe)
    u32 tl = (u32)t, th = (u32)(t >> 32);
    float pl, ph;
    unpack2(p, pl, ph);
    int el = (int)(tl - 0x4B400000u);
    int eh = (int)(th - 0x4B400000u);
    u32 rl = __float_as_uint(pl) + ((u32)el << 23);
    u32 rh = __float_as_uint(ph) + ((u32)eh << 23);
    return pack2(__uint_as_float(rl), __uint_as_float(rh));
}

__global__ __launch_bounds__(TPB)
void kde_partial_kernel(const float* __restrict__ samples,
                        const float* __restrict__ locs) {
    __shared__ ulonglong2 shXY[CHUNK / 2];   // [Sx0,Sx1 | Sy0,Sy1] per 2 samples
    __shared__ u64        shP [CHUNK / 2];   // [P0,P1]
    __shared__ float      wred[TPB / 32];

    const int y     = blockIdx.y;      // 0..63
    const int b     = y >> 5;
    const int chunk = y & 31;
    const int tid   = threadIdx.x;

    if (tid < CHUNK / 2) {
        const float4 s2 = reinterpret_cast<const float4*>(samples)
                              [(b * S_TOT + chunk * CHUNK) / 2 + tid];
        float4 xy = make_float4(2.0f * KLOG * s2.x, 2.0f * KLOG * s2.z,
                                2.0f * KLOG * s2.y, 2.0f * KLOG * s2.w);
        *reinterpret_cast<float4*>(&shXY[tid]) = xy;
        shP[tid] = pack2(-KLOG * (s2.x * s2.x + s2.y * s2.y),
                         -KLOG * (s2.z * s2.z + s2.w * s2.w));
    }
    __syncthreads();

    const int m0 = blockIdx.x * M_TILE + tid;
    const int m1 = m0 + TPB;
    const float2 L0 = reinterpret_cast<const float2*>(locs)[m0];
    const float2 L1 = reinterpret_cast<const float2*>(locs)[m1];
    const u64 Lx0 = pack2(L0.x, L0.x), Ly0 = pack2(L0.y, L0.y);
    const u64 Lx1 = pack2(L1.x, L1.x), Ly1 = pack2(L1.y, L1.y);
    const float q0 = -KLOG * (L0.x * L0.x + L0.y * L0.y);
    const float q1 = -KLOG * (L1.x * L1.x + L1.y * L1.y);
    const u64 qq0 = pack2(q0, q0), qq1 = pack2(q1, q1);

    const u64 MAGIC2    = pack2(12582912.0f, 12582912.0f);
    const u64 NEGMAGIC2 = pack2(-12582912.0f, -12582912.0f);
    const u64 NEGONE2   = pack2(-1.0f, -1.0f);
    const u64 C4 = pack2(0.009618129f, 0.009618129f);
    const u64 C3 = pack2(0.055504109f, 0.055504109f);
    const u64 C2 = pack2(0.240226507f, 0.240226507f);
    const u64 C1 = pack2(0.693147181f, 0.693147181f);
    const u64 C0 = pack2(1.0f, 1.0f);

    u64 accA0 = 0, accA1 = 0;   // location 0 (MUFU path)
    u64 accB0 = 0;              // location 1 (MUFU path)
    u64 accB1 = 0;              // location 1 (poly path)
    #pragma unroll 2
    for (int i = 0; i < CHUNK / 2; i += 2) {
        ulonglong2 xy0 = shXY[i];
        ulonglong2 xy1 = shXY[i + 1];
        u64 p0 = shP[i];
        u64 p1 = shP[i + 1];

        u64 eA0 = add2(fma2(Ly0, xy0.y, fma2(Lx0, xy0.x, p0)), qq0);
        u64 eA1 = add2(fma2(Ly0, xy1.y, fma2(Lx0, xy1.x, p1)), qq0);
        u64 eB0 = add2(fma2(Ly1, xy0.y, fma2(Lx1, xy0.x, p0)), qq1);
        u64 eB1 = add2(fma2(Ly1, xy1.y, fma2(Lx1, xy1.x, p1)), qq1);

        float a0, a1, a2, a3, b0, b1;
        unpack2(eA0, a0, a1);  unpack2(eA1, a2, a3);
        unpack2(eB0, b0, b1);
        accA0 = add2(accA0, pack2(ex2(a0), ex2(a1)));
        accA1 = add2(accA1, pack2(ex2(a2), ex2(a3)));
        accB0 = add2(accB0, pack2(ex2(b0), ex2(b1)));
        accB1 = add2(accB1, exp2_poly2(eB1, MAGIC2, NEGMAGIC2, NEGONE2,
                                       C4, C3, C2, C1, C0));
    }

    float r0, r1, r2, r3;
    unpack2(accA0, r0, r1); unpack2(accA1, r2, r3);
    const float v0 = (r0 + r1) + (r2 + r3);
    unpack2(accB0, r0, r1); unpack2(accB1, r2, r3);
    const float v1 = (r0 + r1) + (r2 + r3);

    // exact fixed-point accumulation (deterministic: integer adds commute)
    atomicAdd(&g_acc[b * M_TOT + m0], __float2ull_rn(v0 * FIXSCALE));
    atomicAdd(&g_acc[b * M_TOT + m1], __float2ull_rn(v1 * FIXSCALE));

    // block contribution to the batch norm (one atomic per block)
    float w = v0 + v1;
    #pragma unroll
    for (int off = 16; off > 0; off >>= 1)
        w += __shfl_xor_sync(0xFFFFFFFFu, w, off);
    if ((tid & 31) == 0) wred[tid >> 5] = w;
    __syncthreads();
    if (tid == 0) {
        float s = 0.f;
        #pragma unroll
        for (int j = 0; j < TPB / 32; j++) s += wred[j];
        atomicAdd(&g_norm[b], __float2ull_rn(s * FIXSCALE));
    }
}

// Finalize: 16K threads, one output each; L2-resident reads;
// self-cleans the accumulators for the next graph replay.
__global__ __launch_bounds__(256)
void kde_finalize_kernel(float* __restrict__ out) {
    const int g = blockIdx.x * 256 + threadIdx.x;  // 0..16383
    const int b = g >> 13;
    const int m = g & (M_TOT - 1);

    const u64 acc  = g_acc[g];
    const u64 nrm  = g_norm[b];
    out[m * B_TOT + b] = (float)acc * (1.0f / (float)nrm);

    g_acc[g] = 0ull;                   // self-clean for next replay
    if (g < B_TOT) g_norm[g] = 0ull;
}

extern "C" void kernel_launch(void* const* d_in, const int* in_sizes, int n_in,
                              void* d_out, int out_size) {
    const float* samples = (const float*)d_in[0];   // (2, 4096, 2) f32
    const float* locs    = (const float*)d_in[1];   // (8192, 2)  f32
    float* out = (float*)d_out;                     // (1, 8192, 2) f32

    dim3 g1(MTILES, NSPLIT * B_TOT);                // (16, 64) = 1024 blocks
    kde_partial_kernel<<<g1, TPB>>>(samples, locs);
    kde_finalize_kernel<<<(M_TOT * B_TOT) / 256, 256>>>(out);
}

// round 17
// speedup vs baseline: 1.0185x; 1.0099x over previous
#include <cuda_runtime.h>

// KDE Gaussian: samples (B=2, S=4096, 2), locations (m=8192, 2)
// out[m,b] = sum_s exp(-|s-l|^2/(2 bw^2));  pdf[m,b] = out[m,b] / sum_m out[m,b]
//
// e = q + P + Lx*Sx + Ly*Sy = -k*dist^2 <= 0  (range-safe)
// HYBRID exp: 6 of 8 exps via MUFU ex2 (packed add2 accumulate), 2 via
// packed-f32x2 polynomial 2^x on the FMA+ALU pipes. 6:2 is the analytic
// optimum: MUFU 48 / FMA ~46 cyc per 8 exps (4:4 -> FMA 60; 8:0 -> MUFU 64;
// 5:3 -> FMA 53; f16x2-MUFU variants -> FMA 56 or f16-accum precision risk).
// Cross-block reduction via exact u64 fixed-point atomics (deterministic:
// integer adds commute; f32 * 2^32 -> u64 is exact).

#define S_TOT   4096
#define M_TOT   8192
#define B_TOT   2
#define NSPLIT  32
#define CHUNK   (S_TOT / NSPLIT)   // 128
#define TPB     256
#define M_TILE  512                // 2 locations per thread
#define MTILES  (M_TOT / M_TILE)   // 16

#define KLOG    18.033688f         // log2(e) / (2*bw^2), bw=0.2
#define FIXSCALE 4294967296.0f     // 2^32

typedef unsigned long long u64;
typedef unsigned int u32;

__device__ u64 g_acc[B_TOT * M_TOT];   // fixed-point sums, zero at entry
__device__ u64 g_norm[B_TOT];          // fixed-point per-batch norms, zero at entry

__device__ __forceinline__ float ex2(float x) {
    float r; asm("ex2.approx.ftz.f32 %0, %1;" : "=f"(r) : "f"(x)); return r;
}
__device__ __forceinline__ u64 pack2(float lo, float hi) {
    u64 r; asm("mov.b64 %0, {%1, %2};" : "=l"(r) : "f"(lo), "f"(hi)); return r;
}
__device__ __forceinline__ void unpack2(u64 v, float& lo, float& hi) {
    asm("mov.b64 {%0, %1}, %2;" : "=f"(lo), "=f"(hi) : "l"(v));
}
__device__ __forceinline__ u64 fma2(u64 a, u64 b, u64 c) {
    u64 d; asm("fma.rn.f32x2 %0, %1, %2, %3;" : "=l"(d) : "l"(a), "l"(b), "l"(c)); return d;
}
__device__ __forceinline__ u64 add2(u64 a, u64 b) {
    u64 d; asm("add.rn.f32x2 %0, %1, %2;" : "=l"(d) : "l"(a), "l"(b)); return d;
}

// Packed 2^x for two lanes, x <= 0 (deg-4 Taylor on [-0.5,0.5]).
__device__ __forceinline__ u64 exp2_poly2(u64 x,
                                          u64 MAGIC2, u64 NEGMAGIC2, u64 NEGONE2,
                                          u64 C4, u64 C3, u64 C2, u64 C1, u64 C0) {
    float xl, xh;
    unpack2(x, xl, xh);
    xl = fmaxf(xl, -126.0f);               // FMNMX (alu pipe)
    xh = fmaxf(xh, -126.0f);
    u64 xc = pack2(xl, xh);
    u64 t  = add2(xc, MAGIC2);             // round-to-int in mantissa
    u64 r  = add2(t, NEGMAGIC2);           // rounded integer value as float
    u64 f  = fma2(r, NEGONE2, xc);         // frac in [-0.5, 0.5]
    u64 p  = fma2(C4, f, C3);
    p = fma2(p, f, C2);
    p = fma2(p, f, C1);
    p = fma2(p, f, C0);
    // splice 2^ei into the float bits (ALU pipe)
    u32 tl = (u32)t, th = (u32)(t >> 32);
    float pl, ph;
    unpack2(p, pl, ph);
    int el = (int)(tl - 0x4B400000u);
    int eh = (int)(th - 0x4B400000u);
    u32 rl = __float_as_uint(pl) + ((u32)el << 23);
    u32 rh = __float_as_uint(ph) + ((u32)eh << 23);
    return pack2(__uint_as_float(rl), __uint_as_float(rh));
}

__global__ __launch_bounds__(TPB)
void kde_partial_kernel(const float* __restrict__ samples,
                        const float* __restrict__ locs) {
    __shared__ ulonglong2 shXY[CHUNK / 2];   // [Sx0,Sx1 | Sy0,Sy1] per 2 samples
    __shared__ u64        shP [CHUNK / 2];   // [P0,P1]
    __shared__ float      wred[TPB / 32];

    const int y     = blockIdx.y;      // 0..63
    const int b     = y >> 5;
    const int chunk = y & 31;
    const int tid   = threadIdx.x;

    if (tid < CHUNK / 2) {
        const float4 s2 = reinterpret_cast<const float4*>(samples)
                              [(b * S_TOT + chunk * CHUNK) / 2 + tid];
        float4 xy = make_float4(2.0f * KLOG * s2.x, 2.0f * KLOG * s2.z,
                                2.0f * KLOG * s2.y, 2.0f * KLOG * s2.w);
        *reinterpret_cast<float4*>(&shXY[tid]) = xy;
        shP[tid] = pack2(-KLOG * (s2.x * s2.x + s2.y * s2.y),
                         -KLOG * (s2.z * s2.z + s2.w * s2.w));
    }
    __syncthreads();

    const int m0 = blockIdx.x * M_TILE + tid;
    const int m1 = m0 + TPB;
    const float2 L0 = reinterpret_cast<const float2*>(locs)[m0];
    const float2 L1 = reinterpret_cast<const float2*>(locs)[m1];
    const u64 Lx0 = pack2(L0.x, L0.x), Ly0 = pack2(L0.y, L0.y);
    const u64 Lx1 = pack2(L1.x, L1.x), Ly1 = pack2(L1.y, L1.y);
    const float q0 = -KLOG * (L0.x * L0.x + L0.y * L0.y);
    const float q1 = -KLOG * (L1.x * L1.x + L1.y * L1.y);
    const u64 qq0 = pack2(q0, q0), qq1 = pack2(q1, q1);

    const u64 MAGIC2    = pack2(12582912.0f, 12582912.0f);
    const u64 NEGMAGIC2 = pack2(-12582912.0f, -12582912.0f);
    const u64 NEGONE2   = pack2(-1.0f, -1.0f);
    const u64 C4 = pack2(0.009618129f, 0.009618129f);
    const u64 C3 = pack2(0.055504109f, 0.055504109f);
    const u64 C2 = pack2(0.240226507f, 0.240226507f);
    const u64 C1 = pack2(0.693147181f, 0.693147181f);
    const u64 C0 = pack2(1.0f, 1.0f);

    u64 accA0 = 0, accA1 = 0;   // location 0 (MUFU path)
    u64 accB0 = 0;              // location 1 (MUFU path)
    u64 accB1 = 0;              // location 1 (poly path)
    #pragma unroll 2
    for (int i = 0; i < CHUNK / 2; i += 2) {
        ulonglong2 xy0 = shXY[i];
        ulonglong2 xy1 = shXY[i + 1];
        u64 p0 = shP[i];
        u64 p1 = shP[i + 1];

        u64 eA0 = add2(fma2(Ly0, xy0.y, fma2(Lx0, xy0.x, p0)), qq0);
        u64 eA1 = add2(fma2(Ly0, xy1.y, fma2(Lx0, xy1.x, p1)), qq0);
        u64 eB0 = add2(fma2(Ly1, xy0.y, fma2(Lx1, xy0.x, p0)), qq1);
        u64 eB1 = add2(fma2(Ly1, xy1.y, fma2(Lx1, xy1.x, p1)), qq1);

        float a0, a1, a2, a3, b0, b1;
        unpack2(eA0, a0, a1);  unpack2(eA1, a2, a3);
        unpack2(eB0, b0, b1);
        accA0 = add2(accA0, pack2(ex2(a0), ex2(a1)));
        accA1 = add2(accA1, pack2(ex2(a2), ex2(a3)));
        accB0 = add2(accB0, pack2(ex2(b0), ex2(b1)));
        accB1 = add2(accB1, exp2_poly2(eB1, MAGIC2, NEGMAGIC2, NEGONE2,
                                       C4, C3, C2, C1, C0));
    }

    float r0, r1, r2, r3;
    unpack2(accA0, r0, r1); unpack2(accA1, r2, r3);
    const float v0 = (r0 + r1) + (r2 + r3);
    unpack2(accB0, r0, r1); unpack2(accB1, r2, r3);
    const float v1 = (r0 + r1) + (r2 + r3);

    // exact fixed-point accumulation (deterministic: integer adds commute)
    atomicAdd(&g_acc[b * M_TOT + m0], __float2ull_rn(v0 * FIXSCALE));
    atomicAdd(&g_acc[b * M_TOT + m1], __float2ull_rn(v1 * FIXSCALE));

    // block contribution to the batch norm (one atomic per block)
    float w = v0 + v1;
    #pragma unroll
    for (int off = 16; off > 0; off >>= 1)
        w += __shfl_xor_sync(0xFFFFFFFFu, w, off);
    if ((tid & 31) == 0) wred[tid >> 5] = w;
    __syncthreads();
    if (tid == 0) {
        float s = 0.f;
        #pragma unroll
        for (int j = 0; j < TPB / 32; j++) s += wred[j];
        atomicAdd(&g_norm[b], __float2ull_rn(s * FIXSCALE));
    }
}

// Finalize: 16K threads, one output each; L2-resident reads;
// self-cleans the accumulators for the next graph replay.
__global__ __launch_bounds__(256)
void kde_finalize_kernel(float* __restrict__ out) {
    const int g = blockIdx.x * 256 + threadIdx.x;  // 0..16383
    const int b = g >> 13;
    const int m = g & (M_TOT - 1);

    const u64 acc  = g_acc[g];
    const u64 nrm  = g_norm[b];
    out[m * B_TOT + b] = (float)acc * (1.0f / (float)nrm);

    g_acc[g] = 0ull;                   // self-clean for next replay
    if (g < B_TOT) g_norm[g] = 0ull;
}

extern "C" void kernel_launch(void* const* d_in, const int* in_sizes, int n_in,
                              void* d_out, int out_size) {
    const float* samples = (const float*)d_in[0];   // (2, 4096, 2) f32
    const float* locs    = (const float*)d_in[1];   // (8192, 2)  f32
    float* out = (float*)d_out;                     // (1, 8192, 2) f32

    dim3 g1(MTILES, NSPLIT * B_TOT);                // (16, 64) = 1024 blocks
    kde_partial_kernel<<<g1, TPB>>>(samples, locs);
    kde_finalize_kernel<<<(M_TOT * B_TOT) / 256, 256>>>(out);
}